// round 16
// baseline (speedup 1.0000x reference)
#include <cuda_runtime.h>
#include <cuda_fp16.h>
#include <cstdint>

#define BATCH   4096
#define DIN     1024
#define DSAE    16384
#define KTOT    262144
#define A_ELEMS (BATCH * DSAE)   /* 67,108,864 */
#define ROW_CAP 1024
#define CAND_CAP 131072
#define BAND    2e-3f

// fixed-range fine histogram for threshold selection
#define HLO   0.8f
#define HHI   2.4f
#define HBINS 8192
#define HSCALE (HBINS / (HHI - HLO))   /* 5120 bins per unit */

// GEMM tiling (single fp16 mma): block 128x128, 8 warps (2x4), warp 64x32
#define BM 128
#define BN 128
#define BK 64
#define NKI (DIN / BK)            /* 16 */
#define RS  144                   /* bytes per smem row: 64 fp16 + 16B pad */
#define AT_B (BM * RS)            /* 18432 */
#define BT_B (BN * RS)            /* 18432 */
#define STAGE_B (AT_B + BT_B)     /* 36864 */
#define GSMEM (2 * STAGE_B)       /* 73728 */
#define ENC_CTAS ((DSAE / BN) * (BATCH / BM))   /* 4096 */

// ---------------- device scratch (static, no allocations) ----------------
__device__ float  g_act[A_ELEMS];      // fp32 activations
__device__ __half g_xh[BATCH * DIN];
__device__ __half g_wh[DSAE * DIN];    // W_enc transposed [N,K] fp16
__device__ float  g_wt[DSAE * DIN];    // W_enc transposed [N,K] fp32 (exact pass)
__device__ __half2 g_wdh[DSAE * DIN / 2];  // W_dec fp16 (decode pass)
__device__ int    g_histF[HBINS];
__device__ int    g_over;              // count of act >= HHI
__device__ int    g_done1;
__device__ float  g_tval;
__device__ int    g_row_cnt[BATCH];
__device__ int    g_row_m[BATCH * ROW_CAP];
__device__ float  g_row_v[BATCH * ROW_CAP];
__device__ int    g_nnz;
__device__ double g_sum;
__device__ int    g_nnz2;
__device__ double g_sum2;
__device__ int    g_cand_n;
__device__ int    g_cand_idx[CAND_CAP];
__device__ float  g_cand_e[CAND_CAP];

// ---------------- PTX helpers ---------------------------------------------
__device__ __forceinline__ uint32_t smem_u32(const void* p) {
    uint32_t a;
    asm("{ .reg .u64 t; cvta.to.shared.u64 t, %1; cvt.u32.u64 %0, t; }" : "=r"(a) : "l"(p));
    return a;
}
__device__ __forceinline__ void cp16(uint32_t dst, const void* src) {
    asm volatile("cp.async.cg.shared.global [%0], [%1], 16;" :: "r"(dst), "l"(src));
}
__device__ __forceinline__ void cp_commit() {
    asm volatile("cp.async.commit_group;" ::: "memory");
}
__device__ __forceinline__ void ldmx4(uint32_t* r, uint32_t addr) {
    asm volatile("ldmatrix.sync.aligned.m8n8.x4.shared.b16 {%0,%1,%2,%3}, [%4];"
                 : "=r"(r[0]), "=r"(r[1]), "=r"(r[2]), "=r"(r[3]) : "r"(addr));
}
__device__ __forceinline__ void mma_fp16(float* d, const uint32_t* a,
                                         uint32_t b0, uint32_t b1) {
    asm volatile("mma.sync.aligned.m16n8k16.row.col.f32.f16.f16.f32 "
                 "{%0,%1,%2,%3}, {%4,%5,%6,%7}, {%8,%9}, {%0,%1,%2,%3};"
                 : "+f"(d[0]), "+f"(d[1]), "+f"(d[2]), "+f"(d[3])
                 : "r"(a[0]), "r"(a[1]), "r"(a[2]), "r"(a[3]), "r"(b0), "r"(b1));
}

// ---------------- zero scratch --------------------------------------------
__global__ void zero_kernel() {
    int i = blockIdx.x * blockDim.x + threadIdx.x;
    if (i < HBINS) g_histF[i] = 0;
    if (i < BATCH) g_row_cnt[i] = 0;
    if (i == 0) {
        g_nnz = 0; g_sum = 0.0; g_nnz2 = 0; g_sum2 = 0.0; g_cand_n = 0;
        g_done1 = 0; g_over = 0; g_tval = HLO;
    }
}

// ---------------- fp32 -> fp16 x -------------------------------------------
__global__ __launch_bounds__(256) void conv_x(const float* __restrict__ x) {
    size_t i = (size_t)blockIdx.x * blockDim.x + threadIdx.x;   // float4 index
    float4 v = ((const float4*)x)[i];
    __half h[4];
    h[0] = __float2half_rn(v.x); h[1] = __float2half_rn(v.y);
    h[2] = __float2half_rn(v.z); h[3] = __float2half_rn(v.w);
    *(uint2*)&g_xh[i * 4] = *(uint2*)h;
}

// ---------------- W_enc [K,N] fp32 -> transposed [N,K] fp16 + fp32 --------
__global__ __launch_bounds__(256) void conv_wt(const float* __restrict__ W) {
    __shared__ __align__(16) float tile[32][132];   // [k][n]
    const int tid = threadIdx.x;
    const int tx = tid & 31, ty = tid >> 5;         // 32 x 8
    const int n0 = blockIdx.x * 128, k0 = blockIdx.y * 32;
#pragma unroll
    for (int j = 0; j < 4; j++) {
        int k = 8 * j + ty;
        float4 v = *(const float4*)&W[(size_t)(k0 + k) * DSAE + n0 + 4 * tx];
        *(float4*)&tile[k][4 * tx] = v;
    }
    __syncthreads();
    const int n  = n0 + (tid >> 1);
    const int nn = tid >> 1;
    const int kk = 16 * (tid & 1);
    float vals[16];
#pragma unroll
    for (int i = 0; i < 16; i++) vals[i] = tile[kk + i][nn];
    __half hh[16];
#pragma unroll
    for (int i = 0; i < 16; i++) hh[i] = __float2half_rn(vals[i]);
    size_t o = (size_t)n * DIN + k0 + kk;
    *(uint4*)&g_wh[o]     = *(uint4*)&hh[0];
    *(uint4*)&g_wh[o + 8] = *(uint4*)&hh[8];
#pragma unroll
    for (int i = 0; i < 4; i++)
        *(float4*)&g_wt[o + 4 * i] = *(float4*)&vals[4 * i];
}

// ---------------- fp16 encode GEMM + fused range-hist + conv_wd + select --
// 128x128 block, 8 warps (2x4), warp tile 64x32, double-buffered cp.async.
// 2 CTAs/SM.  Only ~2% of values land in [HLO,HHI): histogram straight to
// global (no smem mirror — the merge loops cost more than the atomics).
__global__ __launch_bounds__(256, 2) void encode_mma(const float* __restrict__ bias,
                                                     const float* __restrict__ Wd) {
    extern __shared__ char sm[];
    __shared__ int s_sc[256], s_loc[256];
    __shared__ int s_islast;
    const int tid  = threadIdx.x;
    const int wid  = tid >> 5, lane = tid & 31;
    const int wm   = wid >> 2, wn = wid & 3;        // 2 x 4 warps -> 64x32 tiles
    const int m0   = blockIdx.y * BM, n0 = blockIdx.x * BN;
    const uint32_t sbase = smem_u32(sm);

    float acc[4][4][4];
#pragma unroll
    for (int a = 0; a < 4; a++)
#pragma unroll
        for (int b = 0; b < 4; b++)
#pragma unroll
            for (int c = 0; c < 4; c++) acc[a][b][c] = 0.f;

    // stage layout: [A 18432][B 18432]
    auto load_stage = [&](int s, int kt) {
        uint32_t st = sbase + s * STAGE_B;
#pragma unroll
        for (int q = 0; q < 8; q++) {               // 2048 cp16 / 256 thr
            int id = tid + q * 256;
            int r = id >> 3, ch = id & 7;
            uint32_t co = (uint32_t)ch * 16;
            if (r < 128) {
                cp16(st + (uint32_t)r * RS + co,
                     g_xh + (size_t)(m0 + r) * DIN + kt + ch * 8);
            } else {
                int rr = r - 128;
                cp16(st + AT_B + (uint32_t)rr * RS + co,
                     g_wh + (size_t)(n0 + rr) * DIN + kt + ch * 8);
            }
        }
        cp_commit();
    };

    load_stage(0, 0);

    // fold: convert this CTA's slice of W_dec to fp16 (overlaps cp.async wait)
    {
        int cid = blockIdx.y * gridDim.x + blockIdx.x;        // 0..4095
        size_t base4 = (size_t)cid * 1024 + tid;              // float4 units
        const float4* W4 = (const float4*)Wd;
#pragma unroll
        for (int q = 0; q < 4; q++) {
            size_t i = base4 + q * 256;
            float4 v = W4[i];
            g_wdh[i * 2]     = __floats2half2_rn(v.x, v.y);
            g_wdh[i * 2 + 1] = __floats2half2_rn(v.z, v.w);
        }
    }

    auto compute = [&](int s) {
        uint32_t st = sbase + s * STAGE_B;
        uint32_t aT = st, bT = st + AT_B;
        const int lr = lane & 15, lc = lane >> 4;
#pragma unroll
        for (int ks = 0; ks < 4; ks++) {
            const uint32_t koff = (uint32_t)ks * 32 + (uint32_t)lc * 16;
            uint32_t ah[4][4];
#pragma unroll
            for (int mt = 0; mt < 4; mt++) {
                uint32_t ro = (uint32_t)(wm * 64 + mt * 16 + lr) * RS + koff;
                ldmx4(ah[mt], aT + ro);
            }
#pragma unroll
            for (int nt = 0; nt < 2; nt++) {
                uint32_t ro = (uint32_t)(wn * 32 + nt * 16 + lr) * RS + koff;
                uint32_t bf[4];
                ldmx4(bf, bT + ro);
#pragma unroll
                for (int mt = 0; mt < 4; mt++)
#pragma unroll
                    for (int h = 0; h < 2; h++)
                        mma_fp16(acc[mt][nt * 2 + h], ah[mt], bf[h], bf[h + 2]);
            }
        }
    };

    for (int kk = 0; kk < NKI; kk++) {
        if (kk + 1 < NKI) {
            load_stage((kk + 1) & 1, (kk + 1) * BK);
            asm volatile("cp.async.wait_group 1;" ::: "memory");
        } else {
            asm volatile("cp.async.wait_group 0;" ::: "memory");
        }
        __syncthreads();
        compute(kk & 1);
        __syncthreads();
    }

    // epilogue: bias + relu -> fp32 g_act; rare in-range values -> global hist
    const int ncol0 = n0 + wn * 32;
    int over_cnt = 0;
#pragma unroll
    for (int mt = 0; mt < 4; mt++) {
        int mrow = m0 + wm * 64 + mt * 16 + (lane >> 2);
        float* r0 = &g_act[(size_t)mrow * DSAE];
        float* r1 = &g_act[(size_t)(mrow + 8) * DSAE];
#pragma unroll
        for (int g = 0; g < 4; g++) {
            int nc = ncol0 + g * 8 + (lane & 3) * 2;
            float b0 = bias[nc], b1 = bias[nc + 1];
            float2 v0, v1;
            v0.x = fmaxf(acc[mt][g][0] + b0, 0.f);
            v0.y = fmaxf(acc[mt][g][1] + b1, 0.f);
            v1.x = fmaxf(acc[mt][g][2] + b0, 0.f);
            v1.y = fmaxf(acc[mt][g][3] + b1, 0.f);
            *(float2*)&r0[nc] = v0;
            *(float2*)&r1[nc] = v1;
            float vv[4] = {v0.x, v0.y, v1.x, v1.y};
#pragma unroll
            for (int j = 0; j < 4; j++) {
                if (vv[j] >= HLO) {
                    if (vv[j] < HHI) {
                        int idx = (int)((vv[j] - HLO) * HSCALE);
                        if (idx > HBINS - 1) idx = HBINS - 1;
                        atomicAdd(&g_histF[idx], 1);
                    } else {
                        over_cnt++;
                    }
                }
            }
        }
    }
    if (over_cnt) atomicAdd(&g_over, over_cnt);

    // fold: threshold select in the last CTA to finish
    __threadfence();
    __syncthreads();
    if (tid == 0)
        s_islast = (atomicAdd(&g_done1, 1) == ENC_CTAS - 1) ? 1 : 0;
    __syncthreads();
    if (s_islast) {
        const int chunk = HBINS / 256;               // 32 bins per thread
        const int t = tid;
        int sum = 0;
        for (int i = 0; i < chunk; i++) sum += g_histF[t * chunk + i];
        s_loc[t] = sum; s_sc[t] = sum;
        __syncthreads();
        for (int off = 1; off < 256; off <<= 1) {    // suffix sum: s_sc[t] = sum_{u>=t}
            int v = (t + off < 256) ? s_sc[t + off] : 0;
            __syncthreads();
            s_sc[t] += v;
            __syncthreads();
        }
        int over = g_over;
        int high = over + s_sc[t] - s_loc[t];        // count above this chunk
        if (high < KTOT && KTOT <= over + s_sc[t]) { // k-th falls in this chunk
            int accu = high;
            for (int j = chunk - 1; j >= 0; j--) {
                accu += g_histF[t * chunk + j];
                if (accu >= KTOT) {
                    g_tval = HLO + (float)(t * chunk + j) * (1.0f / HSCALE);
                    break;
                }
            }
        }
        if (t == 0 && over >= KTOT) g_tval = HHI;    // degenerate guard
    }
}

// ---------------- band pass: definite members + candidate collection ------
__global__ __launch_bounds__(256) void band_compact(float* __restrict__ z_out,
                                                    int write_z) {
    const float t   = g_tval;
    const float thi = t + BAND;
    float tlo = t - BAND;
    if (tlo < 1e-30f) tlo = 1e-30f;
    size_t stride = (size_t)gridDim.x * blockDim.x;
    const float4* A4 = (const float4*)g_act;
    float lsum = 0.f; int lcnt = 0;
    for (size_t i = (size_t)blockIdx.x * blockDim.x + threadIdx.x;
         i < A_ELEMS / 4; i += stride) {
        float4 v = A4[i];
        float vv[4] = {v.x, v.y, v.z, v.w};
        float zz[4];
        size_t base = i * 4;
#pragma unroll
        for (int j = 0; j < 4; j++) {
            bool keep = vv[j] >= thi;
            zz[j] = keep ? vv[j] : 0.f;
            if (keep) {
                size_t f = base + j;
                int b = (int)(f >> 14);
                int m = (int)(f & 16383);
                int slot = atomicAdd(&g_row_cnt[b], 1);
                if (slot < ROW_CAP) {
                    g_row_m[b * ROW_CAP + slot] = m;
                    g_row_v[b * ROW_CAP + slot] = vv[j];
                }
                lcnt++; lsum += vv[j];
            } else if (vv[j] >= tlo) {
                int c = atomicAdd(&g_cand_n, 1);
                if (c < CAND_CAP) g_cand_idx[c] = (int)(base + j);
            }
        }
        if (write_z) {
            float4 z; z.x = zz[0]; z.y = zz[1]; z.z = zz[2]; z.w = zz[3];
            ((float4*)z_out)[i] = z;
        }
    }
    __shared__ float ssum[256];
    __shared__ int   scnt[256];
    ssum[threadIdx.x] = lsum; scnt[threadIdx.x] = lcnt;
    __syncthreads();
    for (int off = 128; off > 0; off >>= 1) {
        if (threadIdx.x < off) {
            ssum[threadIdx.x] += ssum[threadIdx.x + off];
            scnt[threadIdx.x] += scnt[threadIdx.x + off];
        }
        __syncthreads();
    }
    if (threadIdx.x == 0 && scnt[0]) {
        atomicAdd(&g_nnz, scnt[0]);
        atomicAdd(&g_sum, (double)ssum[0]);
    }
}

// ---------------- exact fp32 recompute of candidates (coalesced W^T) ------
__global__ __launch_bounds__(256) void exact_kernel(const float* __restrict__ x,
                                                    const float* __restrict__ bias) {
    int n_c = min(g_cand_n, CAND_CAP);
    int gw    = (blockIdx.x * blockDim.x + threadIdx.x) >> 5;
    int lane  = threadIdx.x & 31;
    int nwarp = (gridDim.x * blockDim.x) >> 5;
    for (int c = gw; c < n_c; c += nwarp) {
        int flat = g_cand_idx[c];
        int b = flat >> 14, m = flat & 16383;
        const float* xr = x + (size_t)b * DIN;
        const float* wr = g_wt + (size_t)m * DIN;
        float s = 0.f;
#pragma unroll 8
        for (int k = lane; k < DIN; k += 32)
            s += xr[k] * wr[k];
#pragma unroll
        for (int o = 16; o; o >>= 1) s += __shfl_xor_sync(0xFFFFFFFFu, s, o);
        if (lane == 0) g_cand_e[c] = s + bias[m];
    }
}

// ---------------- exact rank-select among candidates ----------------------
__global__ __launch_bounds__(1024) void cand_select(float* __restrict__ z_out,
                                                    int write_z) {
    __shared__ float se[2048];
    __shared__ int s_krem, s_nc;
    if (threadIdx.x == 0) {
        int n_c = min(g_cand_n, CAND_CAP);
        int krem = KTOT - g_nnz;
        if (krem < 0) krem = 0;
        if (krem > n_c) krem = n_c;
        s_krem = krem; s_nc = n_c;
    }
    __syncthreads();
    const int krem = s_krem, n_c = s_nc;
    float lsum = 0.f; int lcnt = 0;
    for (int i0 = blockIdx.x * 1024; i0 < n_c; i0 += gridDim.x * 1024) {
        int i = i0 + threadIdx.x;
        bool valid = (i < n_c);
        float ei = valid ? g_cand_e[i] : 0.f;
        int rank = 0;
        for (int j0 = 0; j0 < n_c; j0 += 2048) {
            int nj = min(2048, n_c - j0);
            __syncthreads();
            for (int j = threadIdx.x; j < nj; j += 1024) se[j] = g_cand_e[j0 + j];
            __syncthreads();
            if (valid)
                for (int j = 0; j < nj; j++) rank += (se[j] > ei);
        }
        if (valid && rank < krem) {
            int flat = g_cand_idx[i];
            int b = flat >> 14, m = flat & 16383;
            if (write_z) z_out[flat] = ei;
            int slot = atomicAdd(&g_row_cnt[b], 1);
            if (slot < ROW_CAP) {
                g_row_m[b * ROW_CAP + slot] = m;
                g_row_v[b * ROW_CAP + slot] = ei;
            }
            lcnt++; lsum += ei;
        }
    }
    if (lcnt) {
        atomicAdd(&g_nnz2, lcnt);
        atomicAdd(&g_sum2, (double)lsum);
    }
}

// ---------------- sparse decode (fp16 W_dec, fp32 accumulate) -------------
__global__ __launch_bounds__(256) void decode_kernel(const float* __restrict__ bdec,
                                                     float* __restrict__ xhat) {
    const int b = blockIdx.x;
    const int t = threadIdx.x;
    const int cnt = min(g_row_cnt[b], ROW_CAP);
    const int c0 = 2 * t, c1 = 2 * t + 512;
    float a00 = bdec[c0], a01 = bdec[c0 + 1];
    float a10 = bdec[c1], a11 = bdec[c1 + 1];
    __shared__ int   sm_m[256];
    __shared__ float sm_v[256];
    for (int i0 = 0; i0 < cnt; i0 += 256) {
        int n = min(256, cnt - i0);
        if (t < n) {
            sm_m[t] = g_row_m[b * ROW_CAP + i0 + t];
            sm_v[t] = g_row_v[b * ROW_CAP + i0 + t];
        }
        __syncthreads();
        for (int i = 0; i < n; i++) {
            const __half2* w2 = g_wdh + (size_t)sm_m[i] * (DIN / 2);
            float v = sm_v[i];
            float2 f0 = __half22float2(w2[t]);
            float2 f1 = __half22float2(w2[t + 256]);
            a00 += v * f0.x; a01 += v * f0.y;
            a10 += v * f1.x; a11 += v * f1.y;
        }
        __syncthreads();
    }
    float* o = xhat + (size_t)b * DIN;
    float2 o0; o0.x = a00; o0.y = a01;
    float2 o1; o1.x = a10; o1.y = a11;
    *(float2*)&o[c0] = o0;
    *(float2*)&o[c1] = o1;
}

// ---------------- scalar metrics ------------------------------------------
__global__ void finalize_kernel(float* scal, int has_scalars) {
    if (threadIdx.x == 0 && has_scalars) {
        int nnz = g_nnz + g_nnz2;
        double sum = g_sum + g_sum2;
        scal[0] = (float)nnz / (float)A_ELEMS;
        scal[1] = (float)(sum / (double)max(nnz, 1));
        scal[2] = (float)nnz;
    }
}

// ---------------- launch ---------------------------------------------------
extern "C" void kernel_launch(void* const* d_in, const int* in_sizes, int n_in,
                              void* d_out, int out_size) {
    const float* x     = (const float*)d_in[0];
    const float* W_enc = (const float*)d_in[1];
    const float* b_enc = (const float*)d_in[2];
    const float* W_dec = (const float*)d_in[3];
    const float* b_dec = (const float*)d_in[4];
    float* out = (float*)d_out;

    const size_t XHAT_N = (size_t)BATCH * DIN;
    const size_t Z_OFF  = XHAT_N;
    const size_t SC_OFF = Z_OFF + (size_t)A_ELEMS;
    int write_z     = ((size_t)out_size >= Z_OFF + (size_t)A_ELEMS) ? 1 : 0;
    int has_scalars = ((size_t)out_size >= SC_OFF + 3) ? 1 : 0;

    cudaFuncSetAttribute(encode_mma,
                         cudaFuncAttributeMaxDynamicSharedMemorySize, GSMEM);

    zero_kernel<<<32, 256>>>();
    conv_x<<<(BATCH * DIN / 4) / 256, 256>>>(x);
    conv_wt<<<dim3(DSAE / 128, DIN / 32), 256>>>(W_enc);
    encode_mma<<<dim3(DSAE / BN, BATCH / BM), 256, GSMEM>>>(b_enc, W_dec);
    band_compact<<<4096, 256>>>(out + Z_OFF, write_z);
    exact_kernel<<<256, 256>>>(x, b_enc);
    cand_select<<<8, 1024>>>(out + Z_OFF, write_z);
    decode_kernel<<<BATCH, 256>>>(b_dec, out);
    finalize_kernel<<<1, 32>>>(out + SC_OFF, has_scalars);
}

// round 17
// speedup vs baseline: 1.4845x; 1.4845x over previous
#include <cuda_runtime.h>
#include <cuda_fp16.h>
#include <cstdint>

#define BATCH   4096
#define DIN     1024
#define DSAE    16384
#define KTOT    262144
#define A_ELEMS (BATCH * DSAE)   /* 67,108,864 */
#define ROW_CAP 1024
#define CAND_CAP 131072
#define BAND    2e-3f

// fixed-range fine histogram for threshold selection
// bin width 1.6/4096 = 3.9e-4  <=  BAND - 2*delta_fp16 (6.7e-4)  ✓
#define HLO   0.8f
#define HHI   2.4f
#define HBINS 4096
#define HSCALE (HBINS / (HHI - HLO))   /* 2560 bins per unit */

// GEMM tiling (single fp16 mma): block 128x128, 8 warps (2x4), warp 64x32
#define BM 128
#define BN 128
#define BK 64
#define NKI (DIN / BK)            /* 16 */
#define RS  144                   /* bytes per smem row: 64 fp16 + 16B pad */
#define AT_B (BM * RS)            /* 18432 */
#define BT_B (BN * RS)            /* 18432 */
#define STAGE_B (AT_B + BT_B)     /* 36864 */
#define GSMEM (2 * STAGE_B)       /* 73728 */
#define ENC_CTAS ((DSAE / BN) * (BATCH / BM))   /* 4096 */

// ---------------- device scratch (static, no allocations) ----------------
__device__ float  g_act[A_ELEMS];      // fp32 activations
__device__ __half g_xh[BATCH * DIN];
__device__ __half g_wh[DSAE * DIN];    // W_enc transposed [N,K] fp16
__device__ float  g_wt[DSAE * DIN];    // W_enc transposed [N,K] fp32 (exact pass)
__device__ __half2 g_wdh[DSAE * DIN / 2];  // W_dec fp16 (decode pass)
__device__ int    g_histF[HBINS];
__device__ int    g_over;              // count of act >= HHI
__device__ int    g_done1;
__device__ float  g_tval;
__device__ int    g_row_cnt[BATCH];
__device__ int    g_row_m[BATCH * ROW_CAP];
__device__ float  g_row_v[BATCH * ROW_CAP];
__device__ int    g_nnz;
__device__ double g_sum;
__device__ int    g_nnz2;
__device__ double g_sum2;
__device__ int    g_cand_n;
__device__ int    g_cand_idx[CAND_CAP];
__device__ float  g_cand_e[CAND_CAP];

// ---------------- PTX helpers ---------------------------------------------
__device__ __forceinline__ uint32_t smem_u32(const void* p) {
    uint32_t a;
    asm("{ .reg .u64 t; cvta.to.shared.u64 t, %1; cvt.u32.u64 %0, t; }" : "=r"(a) : "l"(p));
    return a;
}
__device__ __forceinline__ void cp16(uint32_t dst, const void* src) {
    asm volatile("cp.async.cg.shared.global [%0], [%1], 16;" :: "r"(dst), "l"(src));
}
__device__ __forceinline__ void cp_commit() {
    asm volatile("cp.async.commit_group;" ::: "memory");
}
__device__ __forceinline__ void ldmx4(uint32_t* r, uint32_t addr) {
    asm volatile("ldmatrix.sync.aligned.m8n8.x4.shared.b16 {%0,%1,%2,%3}, [%4];"
                 : "=r"(r[0]), "=r"(r[1]), "=r"(r[2]), "=r"(r[3]) : "r"(addr));
}
__device__ __forceinline__ void mma_fp16(float* d, const uint32_t* a,
                                         uint32_t b0, uint32_t b1) {
    asm volatile("mma.sync.aligned.m16n8k16.row.col.f32.f16.f16.f32 "
                 "{%0,%1,%2,%3}, {%4,%5,%6,%7}, {%8,%9}, {%0,%1,%2,%3};"
                 : "+f"(d[0]), "+f"(d[1]), "+f"(d[2]), "+f"(d[3])
                 : "r"(a[0]), "r"(a[1]), "r"(a[2]), "r"(a[3]), "r"(b0), "r"(b1));
}

// ---------------- zero scratch --------------------------------------------
__global__ void zero_kernel() {
    int i = blockIdx.x * blockDim.x + threadIdx.x;
    if (i < HBINS) g_histF[i] = 0;
    if (i < BATCH) g_row_cnt[i] = 0;
    if (i == 0) {
        g_nnz = 0; g_sum = 0.0; g_nnz2 = 0; g_sum2 = 0.0; g_cand_n = 0;
        g_done1 = 0; g_over = 0; g_tval = HLO;
    }
}

// ---------------- fp32 -> fp16 x -------------------------------------------
__global__ __launch_bounds__(256) void conv_x(const float* __restrict__ x) {
    size_t i = (size_t)blockIdx.x * blockDim.x + threadIdx.x;   // float4 index
    float4 v = ((const float4*)x)[i];
    __half h[4];
    h[0] = __float2half_rn(v.x); h[1] = __float2half_rn(v.y);
    h[2] = __float2half_rn(v.z); h[3] = __float2half_rn(v.w);
    *(uint2*)&g_xh[i * 4] = *(uint2*)h;
}

// ---------------- W_enc [K,N] fp32 -> transposed [N,K] fp16 + fp32 --------
__global__ __launch_bounds__(256) void conv_wt(const float* __restrict__ W) {
    __shared__ __align__(16) float tile[32][132];   // [k][n]
    const int tid = threadIdx.x;
    const int tx = tid & 31, ty = tid >> 5;         // 32 x 8
    const int n0 = blockIdx.x * 128, k0 = blockIdx.y * 32;
#pragma unroll
    for (int j = 0; j < 4; j++) {
        int k = 8 * j + ty;
        float4 v = *(const float4*)&W[(size_t)(k0 + k) * DSAE + n0 + 4 * tx];
        *(float4*)&tile[k][4 * tx] = v;
    }
    __syncthreads();
    const int n  = n0 + (tid >> 1);
    const int nn = tid >> 1;
    const int kk = 16 * (tid & 1);
    float vals[16];
#pragma unroll
    for (int i = 0; i < 16; i++) vals[i] = tile[kk + i][nn];
    __half hh[16];
#pragma unroll
    for (int i = 0; i < 16; i++) hh[i] = __float2half_rn(vals[i]);
    size_t o = (size_t)n * DIN + k0 + kk;
    *(uint4*)&g_wh[o]     = *(uint4*)&hh[0];
    *(uint4*)&g_wh[o + 8] = *(uint4*)&hh[8];
#pragma unroll
    for (int i = 0; i < 4; i++)
        *(float4*)&g_wt[o + 4 * i] = *(float4*)&vals[4 * i];
}

// ---------------- fp16 encode GEMM + fused range-hist + conv_wd + select --
// 128x128 block, 8 warps (2x4), warp tile 64x32, double-buffered cp.async.
// 2 CTAs/SM.  Histogram staged in smem (R15-proven), 4096 bins (halved cost).
__global__ __launch_bounds__(256, 2) void encode_mma(const float* __restrict__ bias,
                                                     const float* __restrict__ Wd) {
    extern __shared__ char sm[];
    __shared__ int s_hist[HBINS];
    __shared__ int s_sc[256], s_loc[256];
    __shared__ int s_islast;
    const int tid  = threadIdx.x;
    const int wid  = tid >> 5, lane = tid & 31;
    const int wm   = wid >> 2, wn = wid & 3;        // 2 x 4 warps -> 64x32 tiles
    const int m0   = blockIdx.y * BM, n0 = blockIdx.x * BN;
    const uint32_t sbase = smem_u32(sm);

    for (int i = tid; i < HBINS; i += 256) s_hist[i] = 0;

    float acc[4][4][4];
#pragma unroll
    for (int a = 0; a < 4; a++)
#pragma unroll
        for (int b = 0; b < 4; b++)
#pragma unroll
            for (int c = 0; c < 4; c++) acc[a][b][c] = 0.f;

    // stage layout: [A 18432][B 18432]
    auto load_stage = [&](int s, int kt) {
        uint32_t st = sbase + s * STAGE_B;
#pragma unroll
        for (int q = 0; q < 8; q++) {               // 2048 cp16 / 256 thr
            int id = tid + q * 256;
            int r = id >> 3, ch = id & 7;
            uint32_t co = (uint32_t)ch * 16;
            if (r < 128) {
                cp16(st + (uint32_t)r * RS + co,
                     g_xh + (size_t)(m0 + r) * DIN + kt + ch * 8);
            } else {
                int rr = r - 128;
                cp16(st + AT_B + (uint32_t)rr * RS + co,
                     g_wh + (size_t)(n0 + rr) * DIN + kt + ch * 8);
            }
        }
        cp_commit();
    };

    load_stage(0, 0);

    // fold: convert this CTA's slice of W_dec to fp16 (overlaps cp.async wait)
    {
        int cid = blockIdx.y * gridDim.x + blockIdx.x;        // 0..4095
        size_t base4 = (size_t)cid * 1024 + tid;              // float4 units
        const float4* W4 = (const float4*)Wd;
#pragma unroll
        for (int q = 0; q < 4; q++) {
            size_t i = base4 + q * 256;
            float4 v = W4[i];
            g_wdh[i * 2]     = __floats2half2_rn(v.x, v.y);
            g_wdh[i * 2 + 1] = __floats2half2_rn(v.z, v.w);
        }
    }

    auto compute = [&](int s) {
        uint32_t st = sbase + s * STAGE_B;
        uint32_t aT = st, bT = st + AT_B;
        const int lr = lane & 15, lc = lane >> 4;
#pragma unroll
        for (int ks = 0; ks < 4; ks++) {
            const uint32_t koff = (uint32_t)ks * 32 + (uint32_t)lc * 16;
            uint32_t ah[4][4];
#pragma unroll
            for (int mt = 0; mt < 4; mt++) {
                uint32_t ro = (uint32_t)(wm * 64 + mt * 16 + lr) * RS + koff;
                ldmx4(ah[mt], aT + ro);
            }
#pragma unroll
            for (int nt = 0; nt < 2; nt++) {
                uint32_t ro = (uint32_t)(wn * 32 + nt * 16 + lr) * RS + koff;
                uint32_t bf[4];
                ldmx4(bf, bT + ro);
#pragma unroll
                for (int mt = 0; mt < 4; mt++)
#pragma unroll
                    for (int h = 0; h < 2; h++)
                        mma_fp16(acc[mt][nt * 2 + h], ah[mt], bf[h], bf[h + 2]);
            }
        }
    };

    for (int kk = 0; kk < NKI; kk++) {
        if (kk + 1 < NKI) {
            load_stage((kk + 1) & 1, (kk + 1) * BK);
            asm volatile("cp.async.wait_group 1;" ::: "memory");
        } else {
            asm volatile("cp.async.wait_group 0;" ::: "memory");
        }
        __syncthreads();
        compute(kk & 1);
        __syncthreads();
    }

    // epilogue: bias + relu -> fp32 g_act; in-range values -> smem hist
    const int ncol0 = n0 + wn * 32;
    int over_cnt = 0;
#pragma unroll
    for (int mt = 0; mt < 4; mt++) {
        int mrow = m0 + wm * 64 + mt * 16 + (lane >> 2);
        float* r0 = &g_act[(size_t)mrow * DSAE];
        float* r1 = &g_act[(size_t)(mrow + 8) * DSAE];
#pragma unroll
        for (int g = 0; g < 4; g++) {
            int nc = ncol0 + g * 8 + (lane & 3) * 2;
            float b0 = bias[nc], b1 = bias[nc + 1];
            float2 v0, v1;
            v0.x = fmaxf(acc[mt][g][0] + b0, 0.f);
            v0.y = fmaxf(acc[mt][g][1] + b1, 0.f);
            v1.x = fmaxf(acc[mt][g][2] + b0, 0.f);
            v1.y = fmaxf(acc[mt][g][3] + b1, 0.f);
            *(float2*)&r0[nc] = v0;
            *(float2*)&r1[nc] = v1;
            float vv[4] = {v0.x, v0.y, v1.x, v1.y};
#pragma unroll
            for (int j = 0; j < 4; j++) {
                if (vv[j] >= HLO) {
                    if (vv[j] < HHI) {
                        int idx = (int)((vv[j] - HLO) * HSCALE);
                        if (idx > HBINS - 1) idx = HBINS - 1;
                        atomicAdd(&s_hist[idx], 1);
                    } else {
                        over_cnt++;
                    }
                }
            }
        }
    }
    if (over_cnt) atomicAdd(&g_over, over_cnt);
    __syncthreads();
    for (int i = tid; i < HBINS; i += 256)
        if (s_hist[i]) atomicAdd(&g_histF[i], s_hist[i]);

    // fold: threshold select in the last CTA to finish
    __threadfence();
    __syncthreads();
    if (tid == 0)
        s_islast = (atomicAdd(&g_done1, 1) == ENC_CTAS - 1) ? 1 : 0;
    __syncthreads();
    if (s_islast) {
        const int chunk = HBINS / 256;               // 16 bins per thread
        const int t = tid;
        int sum = 0;
        for (int i = 0; i < chunk; i++) sum += g_histF[t * chunk + i];
        s_loc[t] = sum; s_sc[t] = sum;
        __syncthreads();
        for (int off = 1; off < 256; off <<= 1) {    // suffix sum: s_sc[t] = sum_{u>=t}
            int v = (t + off < 256) ? s_sc[t + off] : 0;
            __syncthreads();
            s_sc[t] += v;
            __syncthreads();
        }
        int over = g_over;
        int high = over + s_sc[t] - s_loc[t];        // count above this chunk
        if (high < KTOT && KTOT <= over + s_sc[t]) { // k-th falls in this chunk
            int accu = high;
            for (int j = chunk - 1; j >= 0; j--) {
                accu += g_histF[t * chunk + j];
                if (accu >= KTOT) {
                    g_tval = HLO + (float)(t * chunk + j) * (1.0f / HSCALE);
                    break;
                }
            }
        }
        if (t == 0 && over >= KTOT) g_tval = HHI;    // degenerate guard
    }
}

// ---------------- band pass: definite members + candidate collection ------
__global__ __launch_bounds__(256) void band_compact(float* __restrict__ z_out,
                                                    int write_z) {
    const float t   = g_tval;
    const float thi = t + BAND;
    float tlo = t - BAND;
    if (tlo < 1e-30f) tlo = 1e-30f;
    size_t stride = (size_t)gridDim.x * blockDim.x;
    const float4* A4 = (const float4*)g_act;
    float lsum = 0.f; int lcnt = 0;
    for (size_t i = (size_t)blockIdx.x * blockDim.x + threadIdx.x;
         i < A_ELEMS / 4; i += stride) {
        float4 v = A4[i];
        float vv[4] = {v.x, v.y, v.z, v.w};
        float zz[4];
        size_t base = i * 4;
#pragma unroll
        for (int j = 0; j < 4; j++) {
            bool keep = vv[j] >= thi;
            zz[j] = keep ? vv[j] : 0.f;
            if (keep) {
                size_t f = base + j;
                int b = (int)(f >> 14);
                int m = (int)(f & 16383);
                int slot = atomicAdd(&g_row_cnt[b], 1);
                if (slot < ROW_CAP) {
                    g_row_m[b * ROW_CAP + slot] = m;
                    g_row_v[b * ROW_CAP + slot] = vv[j];
                }
                lcnt++; lsum += vv[j];
            } else if (vv[j] >= tlo) {
                int c = atomicAdd(&g_cand_n, 1);
                if (c < CAND_CAP) g_cand_idx[c] = (int)(base + j);
            }
        }
        if (write_z) {
            float4 z; z.x = zz[0]; z.y = zz[1]; z.z = zz[2]; z.w = zz[3];
            ((float4*)z_out)[i] = z;
        }
    }
    __shared__ float ssum[256];
    __shared__ int   scnt[256];
    ssum[threadIdx.x] = lsum; scnt[threadIdx.x] = lcnt;
    __syncthreads();
    for (int off = 128; off > 0; off >>= 1) {
        if (threadIdx.x < off) {
            ssum[threadIdx.x] += ssum[threadIdx.x + off];
            scnt[threadIdx.x] += scnt[threadIdx.x + off];
        }
        __syncthreads();
    }
    if (threadIdx.x == 0 && scnt[0]) {
        atomicAdd(&g_nnz, scnt[0]);
        atomicAdd(&g_sum, (double)ssum[0]);
    }
}

// ---------------- exact fp32 recompute of candidates (coalesced W^T) ------
__global__ __launch_bounds__(256) void exact_kernel(const float* __restrict__ x,
                                                    const float* __restrict__ bias) {
    int n_c = min(g_cand_n, CAND_CAP);
    int gw    = (blockIdx.x * blockDim.x + threadIdx.x) >> 5;
    int lane  = threadIdx.x & 31;
    int nwarp = (gridDim.x * blockDim.x) >> 5;
    for (int c = gw; c < n_c; c += nwarp) {
        int flat = g_cand_idx[c];
        int b = flat >> 14, m = flat & 16383;
        const float* xr = x + (size_t)b * DIN;
        const float* wr = g_wt + (size_t)m * DIN;
        float s = 0.f;
#pragma unroll 8
        for (int k = lane; k < DIN; k += 32)
            s += xr[k] * wr[k];
#pragma unroll
        for (int o = 16; o; o >>= 1) s += __shfl_xor_sync(0xFFFFFFFFu, s, o);
        if (lane == 0) g_cand_e[c] = s + bias[m];
    }
}

// ---------------- exact rank-select among candidates ----------------------
__global__ __launch_bounds__(1024) void cand_select(float* __restrict__ z_out,
                                                    int write_z) {
    __shared__ float se[2048];
    __shared__ int s_krem, s_nc;
    if (threadIdx.x == 0) {
        int n_c = min(g_cand_n, CAND_CAP);
        int krem = KTOT - g_nnz;
        if (krem < 0) krem = 0;
        if (krem > n_c) krem = n_c;
        s_krem = krem; s_nc = n_c;
    }
    __syncthreads();
    const int krem = s_krem, n_c = s_nc;
    float lsum = 0.f; int lcnt = 0;
    for (int i0 = blockIdx.x * 1024; i0 < n_c; i0 += gridDim.x * 1024) {
        int i = i0 + threadIdx.x;
        bool valid = (i < n_c);
        float ei = valid ? g_cand_e[i] : 0.f;
        int rank = 0;
        for (int j0 = 0; j0 < n_c; j0 += 2048) {
            int nj = min(2048, n_c - j0);
            __syncthreads();
            for (int j = threadIdx.x; j < nj; j += 1024) se[j] = g_cand_e[j0 + j];
            __syncthreads();
            if (valid)
                for (int j = 0; j < nj; j++) rank += (se[j] > ei);
        }
        if (valid && rank < krem) {
            int flat = g_cand_idx[i];
            int b = flat >> 14, m = flat & 16383;
            if (write_z) z_out[flat] = ei;
            int slot = atomicAdd(&g_row_cnt[b], 1);
            if (slot < ROW_CAP) {
                g_row_m[b * ROW_CAP + slot] = m;
                g_row_v[b * ROW_CAP + slot] = ei;
            }
            lcnt++; lsum += ei;
        }
    }
    if (lcnt) {
        atomicAdd(&g_nnz2, lcnt);
        atomicAdd(&g_sum2, (double)lsum);
    }
}

// ---------------- sparse decode (fp16 W_dec, fp32 accumulate) -------------
__global__ __launch_bounds__(256) void decode_kernel(const float* __restrict__ bdec,
                                                     float* __restrict__ xhat) {
    const int b = blockIdx.x;
    const int t = threadIdx.x;
    const int cnt = min(g_row_cnt[b], ROW_CAP);
    const int c0 = 2 * t, c1 = 2 * t + 512;
    float a00 = bdec[c0], a01 = bdec[c0 + 1];
    float a10 = bdec[c1], a11 = bdec[c1 + 1];
    __shared__ int   sm_m[256];
    __shared__ float sm_v[256];
    for (int i0 = 0; i0 < cnt; i0 += 256) {
        int n = min(256, cnt - i0);
        if (t < n) {
            sm_m[t] = g_row_m[b * ROW_CAP + i0 + t];
            sm_v[t] = g_row_v[b * ROW_CAP + i0 + t];
        }
        __syncthreads();
        for (int i = 0; i < n; i++) {
            const __half2* w2 = g_wdh + (size_t)sm_m[i] * (DIN / 2);
            float v = sm_v[i];
            float2 f0 = __half22float2(w2[t]);
            float2 f1 = __half22float2(w2[t + 256]);
            a00 += v * f0.x; a01 += v * f0.y;
            a10 += v * f1.x; a11 += v * f1.y;
        }
        __syncthreads();
    }
    float* o = xhat + (size_t)b * DIN;
    float2 o0; o0.x = a00; o0.y = a01;
    float2 o1; o1.x = a10; o1.y = a11;
    *(float2*)&o[c0] = o0;
    *(float2*)&o[c1] = o1;
}

// ---------------- scalar metrics ------------------------------------------
__global__ void finalize_kernel(float* scal, int has_scalars) {
    if (threadIdx.x == 0 && has_scalars) {
        int nnz = g_nnz + g_nnz2;
        double sum = g_sum + g_sum2;
        scal[0] = (float)nnz / (float)A_ELEMS;
        scal[1] = (float)(sum / (double)max(nnz, 1));
        scal[2] = (float)nnz;
    }
}

// ---------------- launch ---------------------------------------------------
extern "C" void kernel_launch(void* const* d_in, const int* in_sizes, int n_in,
                              void* d_out, int out_size) {
    const float* x     = (const float*)d_in[0];
    const float* W_enc = (const float*)d_in[1];
    const float* b_enc = (const float*)d_in[2];
    const float* W_dec = (const float*)d_in[3];
    const float* b_dec = (const float*)d_in[4];
    float* out = (float*)d_out;

    const size_t XHAT_N = (size_t)BATCH * DIN;
    const size_t Z_OFF  = XHAT_N;
    const size_t SC_OFF = Z_OFF + (size_t)A_ELEMS;
    int write_z     = ((size_t)out_size >= Z_OFF + (size_t)A_ELEMS) ? 1 : 0;
    int has_scalars = ((size_t)out_size >= SC_OFF + 3) ? 1 : 0;

    cudaFuncSetAttribute(encode_mma,
                         cudaFuncAttributeMaxDynamicSharedMemorySize, GSMEM);

    zero_kernel<<<32, 256>>>();
    conv_x<<<(BATCH * DIN / 4) / 256, 256>>>(x);
    conv_wt<<<dim3(DSAE / 128, DIN / 32), 256>>>(W_enc);
    encode_mma<<<dim3(DSAE / BN, BATCH / BM), 256, GSMEM>>>(b_enc, W_dec);
    band_compact<<<4096, 256>>>(out + Z_OFF, write_z);
    exact_kernel<<<256, 256>>>(x, b_enc);
    cand_select<<<8, 1024>>>(out + Z_OFF, write_z);
    decode_kernel<<<BATCH, 256>>>(b_dec, out);
    finalize_kernel<<<1, 32>>>(out + SC_OFF, has_scalars);
}